// round 13
// baseline (speedup 1.0000x reference)
#include <cuda_runtime.h>
#include <cstdint>

#define N_NODES 100000
#define N_EDGES 1250000
#define DIM 64
#define NBASES 16
#define E_HALF (N_EDGES / 2)
#define N_TILES32 (N_NODES / 32)        // 3125 exact — no partial tile

// ---------------- scratch (device globals; no allocation allowed) ----------
__device__ float g_S[(size_t)N_NODES * DIM];   // scatter-sum; self-zeroed by final kernel
__device__ float g_deg[N_NODES];               // in-degree; self-zeroed by final kernel
__device__ __align__(16) float2 g_Bp[64 * 64]; // k-pair-packed B: [kp][c]=(B[2kp][c],B[2kp+1][c])
__device__ float g_bm[DIM];
__device__ float g_bs[DIM];

// packed f32x2 FMA: d.lo += a.lo*b.lo ; d.hi += a.hi*b.hi
__device__ __forceinline__ void fma2(unsigned long long& d,
                                     unsigned long long a,
                                     unsigned long long b) {
    asm("fma.rn.f32x2 %0, %1, %2, %0;" : "+l"(d) : "l"(a), "l"(b));
}
__device__ __forceinline__ float pair_sum(unsigned long long v) {
    return __uint_as_float((unsigned)(v & 0xffffffffull)) +
           __uint_as_float((unsigned)(v >> 32));
}

// ---------------- kernel 1: collapse bases into packed weights (~5us) ------
__global__ __launch_bounds__(256) void build_weights(
    const float* __restrict__ wm, const float* __restrict__ bm,
    const float* __restrict__ ws, const float* __restrict__ bs,
    const float* __restrict__ lc) {
    __shared__ float c[NBASES];
    if (threadIdx.x < NBASES) c[threadIdx.x] = lc[threadIdx.x];
    __syncthreads();
    if (blockIdx.x < 16) {
        int idx = blockIdx.x * 256 + threadIdx.x;   // 0..4095
        int kp = idx >> 6;
        int o  = idx & 63;
        const float* base = (kp < 32) ? wm : ws;
        int i0 = (kp < 32) ? 2 * kp : 2 * (kp - 32);
        const float4* p0 = reinterpret_cast<const float4*>(&base[((size_t)i0 * 64 + o) * NBASES]);
        const float4* p1 = reinterpret_cast<const float4*>(&base[((size_t)(i0 + 1) * 64 + o) * NBASES]);
        float lo = 0.f, hi = 0.f;
        #pragma unroll
        for (int q = 0; q < 4; q++) {
            float4 a0 = __ldg(&p0[q]);
            float4 a1 = __ldg(&p1[q]);
            lo = fmaf(a0.x, c[4*q+0], lo); lo = fmaf(a0.y, c[4*q+1], lo);
            lo = fmaf(a0.z, c[4*q+2], lo); lo = fmaf(a0.w, c[4*q+3], lo);
            hi = fmaf(a1.x, c[4*q+0], hi); hi = fmaf(a1.y, c[4*q+1], hi);
            hi = fmaf(a1.z, c[4*q+2], hi); hi = fmaf(a1.w, c[4*q+3], hi);
        }
        g_Bp[idx] = make_float2(lo, hi);
    } else if (threadIdx.x < DIM) {
        int t = threadIdx.x;
        float am = 0.f, as = 0.f;
        #pragma unroll
        for (int b = 0; b < NBASES; b++) {
            am = fmaf(__ldg(&bm[t * NBASES + b]), c[b], am);
            as = fmaf(__ldg(&bs[t * NBASES + b]), c[b], as);
        }
        g_bm[t] = am;
        g_bs[t] = as;
    }
}

// ---------------- kernel 2: edge scatter (R5-proven, ~52us) ----------------
__global__ __launch_bounds__(256) void edge_scatter(
    const float4* __restrict__ x4, const int* __restrict__ ei) {
    int t = blockIdx.x * blockDim.x + threadIdx.x;
    int e = t >> 4;
    if (e >= E_HALF) return;
    int sub = t & 15;
    int e2 = e + E_HALF;
    int src1 = __ldg(&ei[e]);
    int dst1 = __ldg(&ei[N_EDGES + e]);
    int src2 = __ldg(&ei[e2]);
    int dst2 = __ldg(&ei[N_EDGES + e2]);
    float4 v1 = __ldg(&x4[(size_t)src1 * 16 + sub]);
    float4 v2 = __ldg(&x4[(size_t)src2 * 16 + sub]);
    float* p1 = &g_S[(size_t)dst1 * DIM + sub * 4];
    float* p2 = &g_S[(size_t)dst2 * DIM + sub * 4];
    asm volatile("red.global.add.v4.f32 [%0], {%1, %2, %3, %4};"
                 :: "l"(p1), "f"(v1.x), "f"(v1.y), "f"(v1.z), "f"(v1.w) : "memory");
    asm volatile("red.global.add.v4.f32 [%0], {%1, %2, %3, %4};"
                 :: "l"(p2), "f"(v2.x), "f"(v2.y), "f"(v2.z), "f"(v2.w) : "memory");
    if (sub == 0) {
        atomicAdd(&g_deg[dst1], 1.0f);
        atomicAdd(&g_deg[dst2], 1.0f);
    }
}

// ---------------- kernel 3: out = [S|x] @ [Wm;Ws] + deg*bm + bs, L2-norm ---
// 32-node x 64-col tile, 256 threads, 2 rows x 4 cols per thread, f32x2 math.
// B in smem. Small per-thread footprint (~55 regs) so ptxas naturally fits
// >=3 blocks/SM without an occupancy clamp (R6 showed forced 64-reg spills;
// this tile needs no force). Tests the warp-starvation hypothesis behind the
// 92-124us SIMT GEMM plateau. 100000/32=3125 exact: no bounds checks.
// Self-cleans g_S/g_deg for the next launch.
__global__ __launch_bounds__(256) void fused_out(const float* __restrict__ x,
                                                 float* __restrict__ out) {
    __shared__ __align__(16) float2 sB[64 * 64];   // 32KB, same layout as g_Bp
    __shared__ float sbm[DIM], sbs[DIM];

    const int tid = threadIdx.x;

    // Stage B + biases (2048 float4, 8 per thread, coalesced)
    {
        const float4* gB4 = reinterpret_cast<const float4*>(g_Bp);
        float4* sB4 = reinterpret_cast<float4*>(sB);
        #pragma unroll
        for (int i = 0; i < 8; i++) sB4[tid + i * 256] = gB4[tid + i * 256];
        if (tid < DIM) { sbm[tid] = g_bm[tid]; sbs[tid] = g_bs[tid]; }
    }
    __syncthreads();

    const int jj = tid & 15;   // column group: cols j0..j0+3
    const int nn = tid >> 4;   // row group: rows node0+2nn, +1
    const int j0 = jj * 4;
    const int row0 = blockIdx.x * 32 + nn * 2;

    const ulonglong2* __restrict__ S2 = reinterpret_cast<const ulonglong2*>(g_S);
    const ulonglong2* __restrict__ X2 = reinterpret_cast<const ulonglong2*>(x);
    const ulonglong2* sB2 = reinterpret_cast<const ulonglong2*>(sB);
    const int bbase = j0 >> 1;  // ull2 index within a Bp row (32 ull2/row)

    unsigned long long acc[2][4];
    #pragma unroll
    for (int r = 0; r < 2; r++)
        #pragma unroll
        for (int c2 = 0; c2 < 4; c2++) acc[r][c2] = 0ull;

    // ---- K half 1: A = S rows (k 0..63), B pair-rows kp 0..31 ----
    #pragma unroll 4
    for (int k4 = 0; k4 < 16; k4++) {
        ulonglong2 av0 = __ldg(&S2[(size_t)(row0    ) * 16 + k4]);
        ulonglong2 av1 = __ldg(&S2[(size_t)(row0 + 1) * 16 + k4]);
        #pragma unroll
        for (int p = 0; p < 2; p++) {
            int kp = k4 * 2 + p;
            ulonglong2 b01 = sB2[kp * 32 + bbase];
            ulonglong2 b23 = sB2[kp * 32 + bbase + 1];
            unsigned long long a0 = p ? av0.y : av0.x;
            unsigned long long a1 = p ? av1.y : av1.x;
            fma2(acc[0][0], a0, b01.x); fma2(acc[0][1], a0, b01.y);
            fma2(acc[0][2], a0, b23.x); fma2(acc[0][3], a0, b23.y);
            fma2(acc[1][0], a1, b01.x); fma2(acc[1][1], a1, b01.y);
            fma2(acc[1][2], a1, b23.x); fma2(acc[1][3], a1, b23.y);
        }
    }
    // ---- K half 2: A = x rows (k 64..127), B pair-rows kp 32..63 ----
    #pragma unroll 4
    for (int k4 = 0; k4 < 16; k4++) {
        ulonglong2 av0 = __ldg(&X2[(size_t)(row0    ) * 16 + k4]);
        ulonglong2 av1 = __ldg(&X2[(size_t)(row0 + 1) * 16 + k4]);
        #pragma unroll
        for (int p = 0; p < 2; p++) {
            int kp = 32 + k4 * 2 + p;
            ulonglong2 b01 = sB2[kp * 32 + bbase];
            ulonglong2 b23 = sB2[kp * 32 + bbase + 1];
            unsigned long long a0 = p ? av0.y : av0.x;
            unsigned long long a1 = p ? av1.y : av1.x;
            fma2(acc[0][0], a0, b01.x); fma2(acc[0][1], a0, b01.y);
            fma2(acc[0][2], a0, b23.x); fma2(acc[0][3], a0, b23.y);
            fma2(acc[1][0], a1, b01.x); fma2(acc[1][1], a1, b01.y);
            fma2(acc[1][2], a1, b23.x); fma2(acc[1][3], a1, b23.y);
        }
    }

    // Epilogue: fold halves, bias, row L2-norm (across the 16 jj lanes of this
    // half-warp), store, then self-clean this block's g_S rows + g_deg.
    float4* S4 = reinterpret_cast<float4*>(g_S);
    #pragma unroll
    for (int r = 0; r < 2; r++) {
        const int node = row0 + r;
        float deg = __ldg(&g_deg[node]);
        float o[4];
        #pragma unroll
        for (int c = 0; c < 4; c++)
            o[c] = pair_sum(acc[r][c]) + deg * sbm[j0 + c] + sbs[j0 + c];
        float ss = o[0] * o[0] + o[1] * o[1] + o[2] * o[2] + o[3] * o[3];
        #pragma unroll
        for (int off = 8; off > 0; off >>= 1)
            ss += __shfl_xor_sync(0xffffffffu, ss, off);   // within 16-lane half
        float inv = 1.0f / fmaxf(sqrtf(ss), 1e-12f);
        float4 ov = make_float4(o[0] * inv, o[1] * inv, o[2] * inv, o[3] * inv);
        reinterpret_cast<float4*>(out)[(size_t)node * 16 + jj] = ov;
        // Self-clean: this half-warp did all reads of this row above; the
        // shuffle reduction ordered them before these stores.
        S4[(size_t)node * 16 + jj] = make_float4(0.f, 0.f, 0.f, 0.f);
        if (jj == 0) g_deg[node] = 0.f;
    }
}

// ---------------- launch ----------------------------------------------------
extern "C" void kernel_launch(void* const* d_in, const int* in_sizes, int n_in,
                              void* d_out, int out_size) {
    const float* x  = (const float*)d_in[0];
    const int*   ei = (const int*)d_in[1];
    const float* wm = (const float*)d_in[2];
    const float* bm = (const float*)d_in[3];
    const float* ws = (const float*)d_in[4];
    const float* bs = (const float*)d_in[5];
    const float* lc = (const float*)d_in[6];
    float* out = (float*)d_out;

    // collapse bases into packed weights
    build_weights<<<17, 256>>>(wm, bm, ws, bs, lc);
    // edge scatter (g_S/g_deg zero: BSS on first call, self-cleaned after)
    {
        long long tot = (long long)E_HALF * 16;            // 10M threads
        int blocks = (int)((tot + 255) / 256);
        edge_scatter<<<blocks, 256>>>((const float4*)x, ei);
    }
    // fused GEMM + bias + normalize + self-clean (32-node tiles)
    fused_out<<<N_TILES32, 256>>>(x, out);
}